// round 12
// baseline (speedup 1.0000x reference)
#include <cuda_runtime.h>
#include <cstdint>

// Problem constants
#define DMK   1024          // input dim (K of the GEMM)
#define BB    8             // batch (M of the GEMM)
#define VN    32767         // internal nodes = V-1 (N of the GEMM)
#define DEPTH 15
#define TT    1024

// Phase-1 tiling: 8 warps = 2 row-groups x 4 k-teams. Each warp: 128 rows (4/lane),
// 256 k. 4 rows/lane halves the x-broadcast LDS count (the measured LSU binder).
#define NWARPS         8
#define TEAMK          (DMK / 4)                        // 256 k per team
#define KC             16                               // k per chunk
#define NCH            (TEAMK / KC)                     // 16 chunks per warp
#define ROWS_PER_WARP  128
#define ROWS_PER_BLOCK 256
#define STAGES         2
#define WSTAGE         (ROWS_PER_WARP * KC)             // 2048 floats (8 KB), no pad
#define TILE_REGION    (NWARPS * STAGES * WSTAGE)       // 32768 floats
#define XP_REGION      (DMK * BB)                       // 8192 floats (k-pair layout)
#define XCHG_REGION    (2 * 3 * ROWS_PER_WARP * BB)     // 6144 floats
#define SMEM_FLOATS    (TILE_REGION + XP_REGION + XCHG_REGION)  // 47104 = 184 KB
#define NBLOCKS        128                              // single wave (<=148 SMs, occ 1)

// Scratch: sigmoid table S[node][b] (node-major), plus grid-barrier ticket counter.
__device__ float S_buf[32768 * 8];
__device__ int   g_done = 0;   // monotone across graph replays (generation = ticket/128)

// ---------- f32x2 helpers (sm_103a packed fp32 FMA; ptxas never emits from C++) ----
typedef unsigned long long ull;
__device__ __forceinline__ ull packf2(float a, float b) {
    ull r;
    asm("mov.b64 %0, {%1, %2};" : "=l"(r) : "f"(a), "f"(b));
    return r;
}
__device__ __forceinline__ void ffma2(ull& d, ull a, ull b) {
    asm("fma.rn.f32x2 %0, %1, %2, %0;" : "+l"(d) : "l"(a), "l"(b));
}
__device__ __forceinline__ void unpack2(ull v, float& lo, float& hi) {
    asm("mov.b64 {%0, %1}, %2;" : "=f"(lo), "=f"(hi) : "l"(v));
}
__device__ __forceinline__ void cp16(float* sdst, const float* gsrc) {
    uint32_t s = (uint32_t)__cvta_generic_to_shared(sdst);
    asm volatile("cp.async.cg.shared.global [%0], [%1], 16;" :: "r"(s), "l"(gsrc));
}

// ============ Fused: S = sigmoid(W @ x^T + bias), then gather+product ==============
// Block = 256 threads. Warp w: row-group g=w&1 (128 rows, 4/lane: lane, +32, +64, +96),
// k-team t=w>>1 (k in [t*256, t*256+256)). Accumulators are k-parity f32x2 pairs:
// acc[r][b] = (sum even-k, sum odd-k); horizontal add in the epilogue. Tile layout is
// KC=16 floats/row with XOR quad swizzle col=(q ^ ((r>>1)&3)) -> conflict-free for
// both cp.async writes (2 rows/phase in opposite 16-bank halves) and reads (4 even
// lanes XOR-permute [0,16), odd lanes [16,32)). x is read as broadcast LDS.128 from a
// k-pair-major table xP[k2][b] = (x[2k2][b], x[2k2+1][b]). Teams 1-3 publish partials
// to smem; team 0 combines + sigmoid + stores S_buf. Then a ticketed grid barrier
// (single wave) lets the first 32 blocks do the 8192-output gather against hot S_buf.
__global__ void __launch_bounds__(256, 1)
hs_fused(const float* __restrict__ x, const float* __restrict__ W,
         const float* __restrict__ bias, const int* __restrict__ ids,
         float* __restrict__ out) {
    extern __shared__ float sm[];
    const int tid  = threadIdx.x;
    const int lane = tid & 31;
    const int warp = tid >> 5;
    const int g    = warp & 1;   // row group 0..1
    const int t    = warp >> 1;  // k-quarter 0..3

    float* xP   = sm + TILE_REGION;               // xP[k2][b] pairs, 16 floats per k2
    float* xchg = sm + TILE_REGION + XP_REGION;   // partials [g][team-1][row][b]

    // Build k-pair-major x table: xP[k2]: b0e,b0o,b1e,b1o,... (16 floats per k2).
    for (int i = tid; i < DMK * BB; i += 256) {
        int b = i >> 10;            // x is [B, DM] row-major
        int k = i & (DMK - 1);
        xP[(k >> 1) * 16 + b * 2 + (k & 1)] = x[i];
    }
    __syncthreads();

    float*    wtile = sm + warp * STAGES * WSTAGE;
    const int rbw   = blockIdx.x * ROWS_PER_BLOCK + g * ROWS_PER_WARP;
    const int kbase = t * TEAMK;
    const int swz   = (lane >> 1) & 3;   // quad swizzle for this lane's rows (r=lane+32c)

    // Stage one 128-row x 16-k chunk (8 KB) via cp.async. 4 lanes cover one row's 4
    // quads (64 B contiguous); rows clamped at VN-1 (stores suppressed later).
    auto stage = [&](int c, int slot) {
        float* dst = wtile + slot * WSTAGE;
        const float* src = W + kbase + c * KC;
        #pragma unroll
        for (int j = 0; j < 16; ++j) {
            int id = lane + 32 * j;          // 512 float4s per chunk
            int r  = id >> 2;                // row within tile (0..127)
            int q  = id & 3;                 // k-quad (0..3)
            int gr = rbw + r;
            if (gr > VN - 1) gr = VN - 1;
            dst[r * KC + ((q ^ ((r >> 1) & 3)) << 2)];  // (address formula below)
            cp16(dst + r * KC + ((q ^ ((r >> 1) & 3)) << 2),
                 src + (size_t)gr * DMK + q * 4);
        }
        asm volatile("cp.async.commit_group;");
    };

    ull acc[4][8];
    #pragma unroll
    for (int r = 0; r < 4; ++r)
        #pragma unroll
        for (int b = 0; b < 8; ++b) acc[r][b] = 0ull;

    stage(0, 0);
    for (int c = 0; c < NCH; ++c) {
        __syncwarp();  // all lanes done reading the slot we are about to overwrite
        if (c + 1 < NCH) {
            stage(c + 1, (c + 1) & 1);
            asm volatile("cp.async.wait_group 1;");   // chunk c complete
        } else {
            asm volatile("cp.async.wait_group 0;");
        }
        __syncwarp();  // chunk c visible to all lanes

        const float* tb = wtile + (c & 1) * WSTAGE;
        const float* xq = xP + (kbase + c * KC) * 8;  // 16 floats per k2, 32 per quad

        #pragma unroll
        for (int q = 0; q < 4; ++q) {        // logical quad: k = kbase + c*16 + q*4
            const int cq = (q ^ swz) << 2;   // physical column of this lane's rows
            float4 w0 = *(const float4*)(tb + (lane      ) * KC + cq);
            float4 w1 = *(const float4*)(tb + (lane + 32 ) * KC + cq);
            float4 w2 = *(const float4*)(tb + (lane + 64 ) * KC + cq);
            float4 w3 = *(const float4*)(tb + (lane + 96 ) * KC + cq);
            // x for the 2 k2's of this quad, all 8 batches (broadcast, 128B aligned)
            const ulonglong2* xv = (const ulonglong2*)(xq + q * 32);
            ulonglong2 xa0 = xv[0], xa1 = xv[1];   // k2   : b01, b23
            ulonglong2 xa2 = xv[2], xa3 = xv[3];   // k2   : b45, b67
            ulonglong2 xb0 = xv[4], xb1 = xv[5];   // k2+1 : b01, b23
            ulonglong2 xb2 = xv[6], xb3 = xv[7];   // k2+1 : b45, b67

            float4 wr[4] = {w0, w1, w2, w3};
            #pragma unroll
            for (int r = 0; r < 4; ++r) {
                ull wA = packf2(wr[r].x, wr[r].y);   // k2   (even,odd)
                ull wB = packf2(wr[r].z, wr[r].w);   // k2+1 (even,odd)
                ffma2(acc[r][0], wA, xa0.x); ffma2(acc[r][1], wA, xa0.y);
                ffma2(acc[r][2], wA, xa1.x); ffma2(acc[r][3], wA, xa1.y);
                ffma2(acc[r][4], wA, xa2.x); ffma2(acc[r][5], wA, xa2.y);
                ffma2(acc[r][6], wA, xa3.x); ffma2(acc[r][7], wA, xa3.y);
                ffma2(acc[r][0], wB, xb0.x); ffma2(acc[r][1], wB, xb0.y);
                ffma2(acc[r][2], wB, xb1.x); ffma2(acc[r][3], wB, xb1.y);
                ffma2(acc[r][4], wB, xb2.x); ffma2(acc[r][5], wB, xb2.y);
                ffma2(acc[r][6], wB, xb3.x); ffma2(acc[r][7], wB, xb3.y);
            }
        }
    }

    // Horizontal add (even-k + odd-k) -> per-(row,b) scalars.
    float v[4][8];
    #pragma unroll
    for (int r = 0; r < 4; ++r)
        #pragma unroll
        for (int b = 0; b < 8; ++b) {
            float lo, hi; unpack2(acc[r][b], lo, hi);
            v[r][b] = lo + hi;
        }

    // Teams 1-3 publish partials.
    if (t != 0) {
        #pragma unroll
        for (int r = 0; r < 4; ++r) {
            int row = lane + 32 * r;
            float4* dst = (float4*)(xchg + (((g * 3 + (t - 1)) * ROWS_PER_WARP + row) * 8));
            dst[0] = make_float4(v[r][0], v[r][1], v[r][2], v[r][3]);
            dst[1] = make_float4(v[r][4], v[r][5], v[r][6], v[r][7]);
        }
    }
    __syncthreads();

    // Team 0 combines, adds bias, sigmoid, stores S[node][0..7].
    if (t == 0) {
        #pragma unroll
        for (int r = 0; r < 4; ++r) {
            int row = lane + 32 * r;
            int gr  = rbw + row;
            if (gr >= VN) continue;
            float s[8];
            #pragma unroll
            for (int b = 0; b < 8; ++b) s[b] = v[r][b];
            #pragma unroll
            for (int tt = 1; tt < 4; ++tt) {
                const float4* p = (const float4*)(xchg +
                    (((g * 3 + (tt - 1)) * ROWS_PER_WARP + row) * 8));
                float4 pa = p[0], pb = p[1];
                s[0] += pa.x; s[1] += pa.y; s[2] += pa.z; s[3] += pa.w;
                s[4] += pb.x; s[5] += pb.y; s[6] += pb.z; s[7] += pb.w;
            }
            float bb = bias[gr];
            #pragma unroll
            for (int i = 0; i < 8; ++i) {
                float z = s[i] + bb;
                s[i] = 1.0f / (1.0f + __expf(-z));
            }
            float4* dst = (float4*)(S_buf + (size_t)gr * 8);
            dst[0] = make_float4(s[0], s[1], s[2], s[3]);
            dst[1] = make_float4(s[4], s[5], s[6], s[7]);
        }
    }

    // ---- grid barrier (single wave: 128 blocks, occ 1) -------------------------
    __threadfence();        // make this block's S_buf stores visible
    __syncthreads();
    __shared__ int s_target;
    if (tid == 0) {
        int ticket = atomicAdd(&g_done, 1);             // monotone across replays
        s_target = ((ticket >> 7) + 1) << 7;            // end of this generation
    }
    __syncthreads();

    // ---- inline gather: first 32 blocks cover all 8192 outputs -----------------
    if (blockIdx.x < (BB * TT) / 256) {
        if (tid == 0) {
            while (*(volatile int*)&g_done < s_target) { }
        }
        __syncthreads();
        __threadfence();    // acquire: S_buf writes from all blocks now visible

        int idx = blockIdx.x * 256 + tid;               // < 8192
        int b   = idx >> 10;                            // ids/out are [B, T] row-major
        int m   = __ldg(ids + idx) + 32768;             // 1-based heap index of leaf
        // Heap ancestors closed-form: l-th ancestor (leaf-to-root) = (m >> l) - 1.
        float pr0 = 1.0f, pr1 = 1.0f;                   // two chains halve FMUL dep
        #pragma unroll
        for (int l = 1; l <= DEPTH; l += 2)
            pr0 *= S_buf[(size_t)((m >> l) - 1) * 8 + b];
        #pragma unroll
        for (int l = 2; l <= DEPTH; l += 2)
            pr1 *= S_buf[(size_t)((m >> l) - 1) * 8 + b];
        out[idx] = pr0 * pr1;
    }
}

// =================================== launch =======================================
extern "C" void kernel_launch(void* const* d_in, const int* in_sizes, int n_in,
                              void* d_out, int out_size) {
    // Resolve inputs by element count (robust to ordering); x precedes ids among the
    // two 8192-element inputs (setup_inputs dict order).
    const float* x = nullptr; const int* ids = nullptr;
    const float* W = nullptr; const float* bias = nullptr;
    for (int i = 0; i < n_in; ++i) {
        long long s = in_sizes[i];
        if (s == (long long)VN * DMK)       W     = (const float*)d_in[i];
        else if (s == VN)                   bias  = (const float*)d_in[i];
        else if (s == (long long)BB * TT) {
            if (!x) x = (const float*)d_in[i];
            else    ids = (const int*)d_in[i];
        }
    }

    cudaFuncSetAttribute(hs_fused, cudaFuncAttributeMaxDynamicSharedMemorySize,
                         SMEM_FLOATS * 4);
    hs_fused<<<NBLOCKS, 256, SMEM_FLOATS * 4>>>(x, W, bias, ids, (float*)d_out);
}

// round 16
// speedup vs baseline: 1.2085x; 1.2085x over previous
#include <cuda_runtime.h>
#include <cuda.h>
#include <cstdint>

// Problem constants
#define DMK   1024          // input dim (K of the GEMM)
#define BB    8             // batch (M of the GEMM)
#define VN    32767         // internal nodes = V-1 (N of the GEMM)
#define DEPTH 15
#define TT    1024

// Phase-1 tiling: R11 structure (8 warps = 4 row-groups x 2 k-teams; 64 rows/warp,
// 2 rows/lane; 512 k per team) with TMA staging instead of cp.async.
#define NWARPS         8
#define TEAMK          (DMK / 2)                        // 512 k per team
#define KC             32                               // k per chunk (32 f32 = 128 B)
#define NCH            (TEAMK / KC)                     // 16 chunks per warp
#define ROWS_PER_WARP  64
#define ROWS_PER_BLOCK 256
#define STAGES         2
#define WSTAGE         (ROWS_PER_WARP * KC)             // 2048 floats = 8 KB (TMA box)
#define TILE_FLOATS    (NWARPS * STAGES * WSTAGE)       // 32768 floats = 128 KB
#define XT_FLOATS      (DMK * BB)                       // 8192 floats
#define XCHG_FLOATS    (ROWS_PER_BLOCK * BB)            // 2048 floats
#define SMEM_BYTES     ((TILE_FLOATS + XT_FLOATS + XCHG_FLOATS) * 4 + 1024) // +align slack
#define NBLOCKS        128                              // single wave (<=148 SMs, occ 1)
#define CHUNK_BYTES    (WSTAGE * 4)                     // 8192

// Scratch: sigmoid table S[node][b] (node-major), plus grid-barrier ticket counter.
__device__ float S_buf[32768 * 8];
__device__ int   g_done = 0;   // monotone across graph replays (generation = ticket/128)

// ---------- f32x2 helpers (sm_103a packed fp32 FMA; ptxas never emits from C++) ----
typedef unsigned long long ull;
__device__ __forceinline__ ull pack2(float v) {
    ull r; asm("mov.b64 %0, {%1, %1};" : "=l"(r) : "f"(v)); return r;
}
__device__ __forceinline__ void ffma2(ull& d, ull a, ull b) {
    asm("fma.rn.f32x2 %0, %1, %2, %0;" : "+l"(d) : "l"(a), "l"(b));
}
__device__ __forceinline__ void unpack2(ull v, float& lo, float& hi) {
    asm("mov.b64 {%0, %1}, %2;" : "=f"(lo), "=f"(hi) : "l"(v));
}

// ============ Fused: S = sigmoid(W @ x^T + bias), then gather+product ==============
// Block = 256 threads. Warp w: row-group rgrp=w&3 (64 rows, 2/lane: lane, lane+32),
// k-team t=w>>2 (k in [t*512, +512)). W is staged by per-warp double-buffered 2D TMA
// (box 32 f32 x 64 rows, SW128) -> bypasses the L1tex line-fill path that capped
// cp.async at ~18 B/cyc/SM. SW128 smem layout: row r at 128 B pitch, 16 B column
// q ^ (r & 7) -> each 8-lane LDS.128 phase tiles all 32 banks (conflict-free).
// Inner math = proven R4: broadcast x from xT[k][b], per-lane f32x2 accumulators for
// all 8 batches, no cross-lane reduction. Team 1 publishes partials to smem; team 0
// combines + sigmoid + stores S_buf. Ticketed single-wave grid barrier, then the
// first 32 blocks do the 8192-output path-product gather against L2-hot S_buf.
__global__ void __launch_bounds__(256, 1)
hs_fused(const float* __restrict__ x, const float* __restrict__ bias,
         const int* __restrict__ ids, float* __restrict__ out,
         const __grid_constant__ CUtensorMap tmap) {
    extern __shared__ float smraw[];
    __shared__ __align__(8) unsigned long long mbars[NWARPS * STAGES];
    __shared__ int s_target;

    const int tid  = threadIdx.x;
    const int lane = tid & 31;
    const int warp = tid >> 5;
    const int rgrp = warp & 3;   // row group 0..3
    const int team = warp >> 2;  // k-half 0..1

    // 1024 B-align the dynamic smem base (TMA SW128 dst requirement).
    uint32_t rawaddr = (uint32_t)__cvta_generic_to_shared(smraw);
    const int pad = (int)(((1024u - (rawaddr & 1023u)) & 1023u) >> 2);
    float*   sm   = smraw + pad;
    const uint32_t smbase = rawaddr + (uint32_t)(pad * 4);

    float* tiles = sm;                              // [warp][stage][64r x 32k] SW128
    float* xT    = sm + TILE_FLOATS;                // xT[k][b]
    float* xchg  = sm + TILE_FLOATS + XT_FLOATS;    // team-1 partials [row][b]

    // mbarrier init: one per (warp, stage), single arrival (the expect_tx arrive).
    if (tid < NWARPS * STAGES) {
        uint32_t mb = (uint32_t)__cvta_generic_to_shared(&mbars[tid]);
        asm volatile("mbarrier.init.shared.b64 [%0], 1;" :: "r"(mb) : "memory");
    }

    // Transpose x (8x1024 -> k-major, 32 KB); coalesced gmem reads.
    for (int i = tid; i < DMK * BB; i += 256) {
        int b = i >> 10;            // x is [B, DM] row-major
        int k = i & (DMK - 1);
        xT[k * 8 + b] = x[i];
    }
    __syncthreads();

    const int      rbw   = blockIdx.x * ROWS_PER_BLOCK + rgrp * ROWS_PER_WARP;
    const int      kbase = team * TEAMK;
    const uint32_t tbase = smbase + (uint32_t)(warp * STAGES * WSTAGE * 4);

    // Issue one 64-row x 32-k TMA chunk into stage slot (lane 0 only).
    auto stage = [&](int c, int slot) {
        if (lane == 0) {
            uint32_t mb  = (uint32_t)__cvta_generic_to_shared(&mbars[warp * STAGES + slot]);
            uint32_t dst = tbase + (uint32_t)(slot * CHUNK_BYTES);
            asm volatile("mbarrier.arrive.expect_tx.shared.b64 _, [%0], %1;"
                         :: "r"(mb), "r"(CHUNK_BYTES) : "memory");
            asm volatile(
                "cp.async.bulk.tensor.2d.shared::cta.global.tile.mbarrier::complete_tx::bytes "
                "[%0], [%1, {%2, %3}], [%4];"
                :: "r"(dst), "l"(&tmap), "r"(kbase + c * KC), "r"(rbw), "r"(mb)
                : "memory");
        }
    };
    // Wait (all lanes, acquire) for slot's chunk; parity = (c>>1)&1 for slot c&1.
    auto wait_full = [&](int slot, int parity) {
        uint32_t mb = (uint32_t)__cvta_generic_to_shared(&mbars[warp * STAGES + slot]);
        uint32_t done = 0;
        while (!done) {
            asm volatile(
                "{\n\t.reg .pred p;\n\t"
                "mbarrier.try_wait.parity.acquire.cta.shared::cta.b64 p, [%1], %2, 0x989680;\n\t"
                "selp.b32 %0, 1, 0, p;\n\t}"
                : "=r"(done) : "r"(mb), "r"((uint32_t)parity) : "memory");
        }
    };

    ull acc0[4] = {0ull, 0ull, 0ull, 0ull};
    ull acc1[4] = {0ull, 0ull, 0ull, 0ull};

    stage(0, 0);
    const int sw = lane & 7;   // SW128 column xor for this lane's rows (r&7 == lane&7)
    for (int c = 0; c < NCH; ++c) {
        __syncwarp();                       // all lanes done with slot being reused
        if (c + 1 < NCH) stage(c + 1, (c + 1) & 1);
        wait_full(c & 1, (c >> 1) & 1);     // chunk c landed (acquire)

        const float* tb = tiles + (warp * STAGES + (c & 1)) * WSTAGE;
        const float* xk = xT + (kbase + c * KC) * 8;

        #pragma unroll
        for (int kk = 0; kk < KC; kk += 4) {
            const int col = (((kk >> 2) ^ sw) << 2);           // swizzled 16 B column
            float4 w0 = *(const float4*)(tb + lane * KC + col);         // row lane
            float4 w1 = *(const float4*)(tb + (lane + 32) * KC + col);  // row lane+32
            float w0a[4] = {w0.x, w0.y, w0.z, w0.w};
            float w1a[4] = {w1.x, w1.y, w1.z, w1.w};
            #pragma unroll
            for (int j = 0; j < 4; ++j) {
                const double2 xab = *(const double2*)(xk + (kk + j) * 8);      // b0..b3
                const double2 xcd = *(const double2*)(xk + (kk + j) * 8 + 4);  // b4..b7
                ull x01 = __double_as_longlong(xab.x);
                ull x23 = __double_as_longlong(xab.y);
                ull x45 = __double_as_longlong(xcd.x);
                ull x67 = __double_as_longlong(xcd.y);
                ull p0 = pack2(w0a[j]);
                ffma2(acc0[0], p0, x01); ffma2(acc0[1], p0, x23);
                ffma2(acc0[2], p0, x45); ffma2(acc0[3], p0, x67);
                ull p1 = pack2(w1a[j]);
                ffma2(acc1[0], p1, x01); ffma2(acc1[1], p1, x23);
                ffma2(acc1[2], p1, x45); ffma2(acc1[3], p1, x67);
            }
        }
    }

    // Team 1 publishes its partial dot products to smem.
    if (team == 1) {
        #pragma unroll
        for (int rr = 0; rr < 2; ++rr) {
            const ull* acc = (rr == 0) ? acc0 : acc1;
            int rl = rgrp * 64 + lane + rr * 32;       // row within block
            float s[8];
            #pragma unroll
            for (int p = 0; p < 4; ++p) unpack2(acc[p], s[2 * p], s[2 * p + 1]);
            float4* dst = (float4*)(xchg + rl * 8);
            dst[0] = make_float4(s[0], s[1], s[2], s[3]);
            dst[1] = make_float4(s[4], s[5], s[6], s[7]);
        }
    }
    __syncthreads();

    // Team 0 combines, adds bias, applies sigmoid, stores S[node][0..7].
    if (team == 0) {
        #pragma unroll
        for (int rr = 0; rr < 2; ++rr) {
            int gr = rbw + lane + rr * 32;
            if (gr >= VN) continue;
            const ull* acc = (rr == 0) ? acc0 : acc1;
            int rl = rgrp * 64 + lane + rr * 32;
            const float4* prt = (const float4*)(xchg + rl * 8);
            float4 pa = prt[0], pb = prt[1];
            float bb = bias[gr];
            float s[8];
            #pragma unroll
            for (int p = 0; p < 4; ++p) unpack2(acc[p], s[2 * p], s[2 * p + 1]);
            s[0] += pa.x; s[1] += pa.y; s[2] += pa.z; s[3] += pa.w;
            s[4] += pb.x; s[5] += pb.y; s[6] += pb.z; s[7] += pb.w;
            #pragma unroll
            for (int i = 0; i < 8; ++i) {
                float z = s[i] + bb;
                s[i] = 1.0f / (1.0f + __expf(-z));
            }
            float4* dst = (float4*)(S_buf + (size_t)gr * 8);
            dst[0] = make_float4(s[0], s[1], s[2], s[3]);
            dst[1] = make_float4(s[4], s[5], s[6], s[7]);
        }
    }

    // ---- grid barrier (single wave: 128 blocks, occ 1) -------------------------
    __threadfence();        // make this block's S_buf stores visible
    __syncthreads();
    if (tid == 0) {
        int ticket = atomicAdd(&g_done, 1);             // monotone across replays
        s_target = ((ticket >> 7) + 1) << 7;            // end of this generation
    }
    __syncthreads();

    // ---- inline gather: first 32 blocks cover all 8192 outputs -----------------
    if (blockIdx.x < (BB * TT) / 256) {
        if (tid == 0) {
            while (*(volatile int*)&g_done < s_target) { }
        }
        __syncthreads();
        __threadfence();    // acquire: S_buf writes from all blocks now visible

        int idx = blockIdx.x * 256 + tid;               // < 8192
        int b   = idx >> 10;                            // ids/out are [B, T] row-major
        int m   = __ldg(ids + idx) + 32768;             // 1-based heap index of leaf
        // Heap ancestors closed-form: l-th ancestor (leaf-to-root) = (m >> l) - 1.
        float pr0 = 1.0f, pr1 = 1.0f;                   // two chains halve FMUL dep
        #pragma unroll
        for (int l = 1; l <= DEPTH; l += 2)
            pr0 *= S_buf[(size_t)((m >> l) - 1) * 8 + b];
        #pragma unroll
        for (int l = 2; l <= DEPTH; l += 2)
            pr1 *= S_buf[(size_t)((m >> l) - 1) * 8 + b];
        out[idx] = pr0 * pr1;
    }
}

// =================================== launch =======================================
// Manual PFN typedef: some cuda.h versions don't expose PFN_cuTensorMapEncodeTiled
// (it lives in cudaTypedefs.h). Note the OOB-fill enum's real name is
// CUtensorMapFloatOOBfill (NOT CUtensorMapOOBfill).
typedef CUresult (*tmap_encode_fn)(
    CUtensorMap*, CUtensorMapDataType, cuuint32_t, void*,
    const cuuint64_t*, const cuuint64_t*, const cuuint32_t*, const cuuint32_t*,
    CUtensorMapInterleave, CUtensorMapSwizzle, CUtensorMapL2promotion,
    CUtensorMapFloatOOBfill);

extern "C" void kernel_launch(void* const* d_in, const int* in_sizes, int n_in,
                              void* d_out, int out_size) {
    // Resolve inputs by element count (robust to ordering); x precedes ids among the
    // two 8192-element inputs (setup_inputs dict order).
    const float* x = nullptr; const int* ids = nullptr;
    const float* W = nullptr; const float* bias = nullptr;
    for (int i = 0; i < n_in; ++i) {
        long long s = in_sizes[i];
        if (s == (long long)VN * DMK)       W     = (const float*)d_in[i];
        else if (s == VN)                   bias  = (const float*)d_in[i];
        else if (s == (long long)BB * TT) {
            if (!x) x = (const float*)d_in[i];
            else    ids = (const int*)d_in[i];
        }
    }

    // Build the W tensor map (2D f32 [1024, 32767], box 32x64, SW128). Fetch the
    // driver API via the runtime entry-point query (no -lcuda link dependency).
    CUtensorMap tmap;
    {
        tmap_encode_fn encode = nullptr;
        cudaDriverEntryPointQueryResult st;
        cudaGetDriverEntryPointByVersion("cuTensorMapEncodeTiled", (void**)&encode,
                                         12000, cudaEnableDefault, &st);
        cuuint64_t dims[2]    = {DMK, VN};          // {k floats, rows}
        cuuint64_t strides[1] = {DMK * 4};          // row pitch in bytes
        cuuint32_t box[2]     = {KC, ROWS_PER_WARP};// 32 f32 = 128 B x 64 rows
        cuuint32_t estr[2]    = {1, 1};
        encode(&tmap, CU_TENSOR_MAP_DATA_TYPE_FLOAT32, 2, (void*)W,
               dims, strides, box, estr,
               CU_TENSOR_MAP_INTERLEAVE_NONE, CU_TENSOR_MAP_SWIZZLE_128B,
               CU_TENSOR_MAP_L2_PROMOTION_L2_128B, CU_TENSOR_MAP_FLOAT_OOB_FILL_NONE);
    }

    cudaFuncSetAttribute(hs_fused, cudaFuncAttributeMaxDynamicSharedMemorySize,
                         SMEM_BYTES);
    hs_fused<<<NBLOCKS, 256, SMEM_BYTES>>>(x, bias, ids, (float*)d_out, tmap);
}